// round 4
// baseline (speedup 1.0000x reference)
#include <cuda_runtime.h>
#include <cuda_bf16.h>
#include <stdint.h>

// ---------------- problem constants ----------------
#define DIM        512
#define NPAIR      8192
#define TILE       128
#define NTILES     64             // 8192 / 128
#define TILES_PER_CTA 32          // j-tiles per CTA (2 halves of anchor range)
#define NKC        4              // K chunks of 128 int8 (128 B per row) each
#define BLK_BYTES  16384          // 128 rows x 128 bytes
#define NABUF      4              // anchor-chunk ring depth
#define TOTAL_CHUNKS (TILES_PER_CTA * NKC)   // 128
#define QSCALE     512.0f
#define INV_S2     (1.0f / 262144.0f)        // 1/512^2 (exact power of two)

// ---------------- smem layout (offsets from 1024-aligned base) ----------------
#define SM_P       0
#define SM_AB      (SM_P + NKC * BLK_BYTES)          // 65536
#define SM_RED     (SM_AB + NABUF * BLK_BYTES)       // 131072
#define SM_END     (SM_RED + 128 * 4 * 4)            // 133120
#define SM_DYN     (SM_END + 1024)

// ---------------- device scratch (static: allowed) ----------------
__device__ int8_t g_P[(size_t)NPAIR * DIM];   // quantized positive rows
__device__ int8_t g_A[(size_t)NPAIR * DIM];   // quantized anchor rows
__device__ float g_partial[2 * NPAIR];        // per-half row exp-sums
__device__ float g_diag[NPAIR];               // fp32 cos_ii
__device__ float g_blk[32];                   // finalize stage-1 partials

// ---------------- PTX helpers (base-ISA only) ----------------
static __device__ __forceinline__ uint32_t smem_u32(const void* p) {
    uint32_t a;
    asm("{ .reg .u64 t; cvta.to.shared.u64 t, %1; cvt.u32.u64 %0, t; }"
        : "=r"(a) : "l"(p));
    return a;
}

#define CPA16(dst, src) \
    asm volatile("cp.async.cg.shared.global [%0], [%1], 16;" :: "r"(dst), "l"(src))
#define CPA_COMMIT() asm volatile("cp.async.commit_group;" ::: "memory")
#define CPA_WAIT2()  asm volatile("cp.async.wait_group 2;" ::: "memory")

#define LDSM4(r0, r1, r2, r3, addr) \
    asm volatile("ldmatrix.sync.aligned.m8n8.x4.shared.b16 {%0,%1,%2,%3}, [%4];" \
                 : "=r"(r0), "=r"(r1), "=r"(r2), "=r"(r3) : "r"(addr))

// s8 x s8 -> s32, K=32 per instruction. Fragment bytes are laid out exactly like
// the bf16 m16n8k16 fragment (each b16 = 2 k-contiguous int8), so ldmatrix.b16
// addressing is reused unchanged.
static __device__ __forceinline__ void mma_s8(int* d, const uint32_t* a,
                                              const uint32_t* b) {
    asm volatile(
        "mma.sync.aligned.m16n8k32.row.col.s32.s8.s8.s32 "
        "{%0,%1,%2,%3}, {%4,%5,%6,%7}, {%8,%9}, {%0,%1,%2,%3};"
        : "+r"(d[0]), "+r"(d[1]), "+r"(d[2]), "+r"(d[3])
        : "r"(a[0]), "r"(a[1]), "r"(a[2]), "r"(a[3]), "r"(b[0]), "r"(b[1]));
}

static __device__ __forceinline__ uint32_t pack4(float4 v, float s) {
    int q0 = __float2int_rn(fminf(fmaxf(v.x * s, -127.f), 127.f));
    int q1 = __float2int_rn(fminf(fmaxf(v.y * s, -127.f), 127.f));
    int q2 = __float2int_rn(fminf(fmaxf(v.z * s, -127.f), 127.f));
    int q3 = __float2int_rn(fminf(fmaxf(v.w * s, -127.f), 127.f));
    return (uint32_t)(q0 & 255) | ((uint32_t)(q1 & 255) << 8) |
           ((uint32_t)(q2 & 255) << 16) | ((uint32_t)(q3 & 255) << 24);
}

// ---------------- kernel 1: per-pair normalize + quantize + fp32 diag ----------------
// One warp per pair: reads anchor (row 2i) and positive (row 2i+1) once,
// computes both norms + the pair dot in fp32, writes quantized rows + g_diag.
__global__ void __launch_bounds__(256) prep_kernel(const float* __restrict__ x) {
    int pair = blockIdx.x * 8 + (threadIdx.x >> 5);
    int lid = threadIdx.x & 31;
    const float4* ar = (const float4*)(x + (size_t)(2 * pair) * DIM);
    const float4* pr = (const float4*)(x + (size_t)(2 * pair + 1) * DIM);
    float4 va[4], vp[4];
    float ssa = 0.f, ssp = 0.f, dp = 0.f;
#pragma unroll
    for (int i = 0; i < 4; i++) {
        va[i] = ar[lid + i * 32];
        vp[i] = pr[lid + i * 32];
        ssa += va[i].x * va[i].x + va[i].y * va[i].y + va[i].z * va[i].z + va[i].w * va[i].w;
        ssp += vp[i].x * vp[i].x + vp[i].y * vp[i].y + vp[i].z * vp[i].z + vp[i].w * vp[i].w;
        dp  += va[i].x * vp[i].x + va[i].y * vp[i].y + va[i].z * vp[i].z + va[i].w * vp[i].w;
    }
#pragma unroll
    for (int o = 16; o; o >>= 1) {
        ssa += __shfl_xor_sync(0xffffffffu, ssa, o);
        ssp += __shfl_xor_sync(0xffffffffu, ssp, o);
        dp  += __shfl_xor_sync(0xffffffffu, dp, o);
    }
    float inva = rsqrtf(ssa);   // norms ~sqrt(512): EPS clamp never binds
    float invp = rsqrtf(ssp);
    if (lid == 0) g_diag[pair] = dp * inva * invp;

    uint32_t* da = (uint32_t*)(g_A + (size_t)pair * DIM);
    uint32_t* dq = (uint32_t*)(g_P + (size_t)pair * DIM);
    float sa = inva * QSCALE, sp = invp * QSCALE;
#pragma unroll
    for (int i = 0; i < 4; i++) {
        da[lid + i * 32] = pack4(va[i], sa);
        dq[lid + i * 32] = pack4(vp[i], sp);
    }
}

// ---------------- kernel 2: fused cos-GEMM (mma.sync s8) + exp row-sums ----------------
__global__ void __launch_bounds__(256, 1) angle_main(const float* __restrict__ wp) {
    extern __shared__ char smem_raw[];
    uint32_t sb_raw = smem_u32(smem_raw);
    uint32_t pad = ((sb_raw + 1023u) & ~1023u) - sb_raw;
    char* smem = smem_raw + pad;
    uint32_t sbase = sb_raw + pad;

    const int tid = threadIdx.x, wid = tid >> 5, lid = tid & 31;
    const int wm = wid >> 2, wn = wid & 3;         // 2 x 4 warp grid
    const int it = blockIdx.x >> 1;                // i-tile (positive rows)
    const int half = blockIdx.x & 1;               // anchor half
    const float wexp = (*wp) * INV_S2;             // acc(s32) -> w*cos

    // ldmatrix lane geometry (xor-swizzled 16B chunks within 128B rows)
    const int a_row0 = wm * 64 + (lid & 7) + ((lid >> 3) & 1) * 8;  // + mf*16
    const int a_k = lid >> 4;
    const int a_sw = a_row0 & 7;
    const int b_row0 = wn * 32 + (lid & 7) + ((lid >> 4) & 1) * 8;  // + p*16
    const int b_k = (lid >> 3) & 1;
    const int b_sw = b_row0 & 7;

    // ---- resident P tile: 4 swizzled chunks of [128 rows x 128 B] ----
    {
        const char* src = (const char*)(g_P + (size_t)it * TILE * DIM);
        for (int i = tid; i < NKC * 1024; i += 256) {
            int blk = i >> 10, v = i & 1023;
            int row = v >> 3, c = v & 7;
            CPA16(sbase + SM_P + blk * BLK_BYTES + row * 128 + ((c ^ (row & 7)) << 4),
                  src + (size_t)row * DIM + blk * 128 + c * 16);
        }
        CPA_COMMIT();
    }

    // issue first 3 anchor chunks
#pragma unroll
    for (int c = 0; c < 3; ++c) {
        int jt = half * TILES_PER_CTA + (c >> 2), kc = c & 3;
        const char* src = (const char*)(g_A + (size_t)jt * TILE * DIM) + kc * 128;
        uint32_t dst = sbase + SM_AB + (c & (NABUF - 1)) * BLK_BYTES;
        for (int u = tid; u < 1024; u += 256) {
            int row = u >> 3, cc = u & 7;
            CPA16(dst + row * 128 + ((cc ^ (row & 7)) << 4),
                  src + (size_t)row * DIM + cc * 16);
        }
        CPA_COMMIT();
    }

    int acc[4][4][4];
#pragma unroll
    for (int mf = 0; mf < 4; mf++)
#pragma unroll
        for (int nf = 0; nf < 4; nf++)
#pragma unroll
            for (int k = 0; k < 4; k++) acc[mf][nf][k] = 0;
    float rs[8];
#pragma unroll
    for (int r = 0; r < 8; r++) rs[r] = 0.f;

#pragma unroll 1
    for (int c = 0; c < TOTAL_CHUNKS; ++c) {
        CPA_WAIT2();
        __syncthreads();

        // issue chunk c+3 (empty commit keeps group counting aligned)
        {
            int cn = c + 3;
            if (cn < TOTAL_CHUNKS) {
                int jt = half * TILES_PER_CTA + (cn >> 2), kc = cn & 3;
                const char* src = (const char*)(g_A + (size_t)jt * TILE * DIM) + kc * 128;
                uint32_t dst = sbase + SM_AB + (cn & (NABUF - 1)) * BLK_BYTES;
                for (int u = tid; u < 1024; u += 256) {
                    int row = u >> 3, cc = u & 7;
                    CPA16(dst + row * 128 + ((cc ^ (row & 7)) << 4),
                          src + (size_t)row * DIM + cc * 16);
                }
            }
            CPA_COMMIT();
        }

        // ---- compute chunk c: 128 k-elems = 4 mma k-steps of K=32 ----
        const uint32_t pb = sbase + SM_P + (c & 3) * BLK_BYTES;
        const uint32_t bb = sbase + SM_AB + (c & (NABUF - 1)) * BLK_BYTES;
#pragma unroll
        for (int ks = 0; ks < 4; ++ks) {
            uint32_t a[4][4];
#pragma unroll
            for (int mf = 0; mf < 4; ++mf) {
                uint32_t addr = pb + (uint32_t)(a_row0 + mf * 16) * 128 +
                                (uint32_t)(((2 * ks + a_k) ^ a_sw) << 4);
                LDSM4(a[mf][0], a[mf][1], a[mf][2], a[mf][3], addr);
            }
            uint32_t b[4][2];
#pragma unroll
            for (int p = 0; p < 2; ++p) {
                uint32_t addr = bb + (uint32_t)(b_row0 + p * 16) * 128 +
                                (uint32_t)(((2 * ks + b_k) ^ b_sw) << 4);
                uint32_t r0, r1, r2, r3;
                LDSM4(r0, r1, r2, r3, addr);
                b[2 * p][0] = r0; b[2 * p][1] = r1;
                b[2 * p + 1][0] = r2; b[2 * p + 1][1] = r3;
            }
#pragma unroll
            for (int mf = 0; mf < 4; ++mf)
#pragma unroll
                for (int nf = 0; nf < 4; ++nf)
                    mma_s8(acc[mf][nf], a[mf], b[nf]);
        }

        // ---- per-j-tile epilogue: exp-accumulate, reset accumulators ----
        if ((c & 3) == 3) {
#pragma unroll
            for (int mf = 0; mf < 4; ++mf)
#pragma unroll
                for (int nf = 0; nf < 4; ++nf) {
                    rs[mf * 2 + 0] += __expf((float)acc[mf][nf][0] * wexp) +
                                      __expf((float)acc[mf][nf][1] * wexp);
                    rs[mf * 2 + 1] += __expf((float)acc[mf][nf][2] * wexp) +
                                      __expf((float)acc[mf][nf][3] * wexp);
#pragma unroll
                    for (int k = 0; k < 4; k++) acc[mf][nf][k] = 0;
                }
        }
    }

    // ---- deterministic CTA reduction: lanes -> warps -> rows ----
#pragma unroll
    for (int r = 0; r < 8; ++r) {
        rs[r] += __shfl_xor_sync(0xffffffffu, rs[r], 1);
        rs[r] += __shfl_xor_sync(0xffffffffu, rs[r], 2);
    }
    float* red = (float*)(smem + SM_RED);
    __syncthreads();
    if ((lid & 3) == 0) {
        int g = lid >> 2;
#pragma unroll
        for (int mf = 0; mf < 4; ++mf) {
            int rl0 = wm * 64 + mf * 16 + g;
            red[(rl0) * 4 + wn] = rs[mf * 2 + 0];
            red[(rl0 + 8) * 4 + wn] = rs[mf * 2 + 1];
        }
    }
    __syncthreads();
    if (tid < 128) {
        float s = red[tid * 4 + 0] + red[tid * 4 + 1] + red[tid * 4 + 2] + red[tid * 4 + 3];
        g_partial[half * NPAIR + it * TILE + tid] = s;
    }
}

// ---------------- kernel 3: per-row log + block partial (32 CTAs) ----------------
__global__ void __launch_bounds__(256) lse_kernel(const float* __restrict__ wp) {
    __shared__ float red[256];
    int tid = threadIdx.x;
    int i = blockIdx.x * 256 + tid;
    float w = *wp;
    float es = g_partial[i] + g_partial[NPAIR + i];
    red[tid] = logf(es) - w * g_diag[i];
    __syncthreads();
    for (int o = 128; o; o >>= 1) {
        if (tid < o) red[tid] += red[tid + o];
        __syncthreads();
    }
    if (tid == 0) g_blk[blockIdx.x] = red[0];
}

// ---------------- kernel 4: final scalar ----------------
__global__ void finalize_kernel(float* __restrict__ out) {
    int lid = threadIdx.x;
    float s = g_blk[lid];
#pragma unroll
    for (int o = 16; o; o >>= 1) s += __shfl_xor_sync(0xffffffffu, s, o);
    if (lid == 0) out[0] = s / (float)NPAIR;
}

// ---------------- launch ----------------
extern "C" void kernel_launch(void* const* d_in, const int* in_sizes, int n_in,
                              void* d_out, int out_size) {
    const float* x = (const float*)d_in[0];
    const float* wp = (const float*)d_in[1];
    // b cancels analytically: lse_i - logit_ii is independent of b.

    cudaFuncSetAttribute(angle_main, cudaFuncAttributeMaxDynamicSharedMemorySize, SM_DYN);

    prep_kernel<<<NPAIR / 8, 256>>>(x);
    angle_main<<<NTILES * 2, 256, SM_DYN>>>(wp);
    lse_kernel<<<32, 256>>>(wp);
    finalize_kernel<<<1, 32>>>((float*)d_out);
}

// round 5
// speedup vs baseline: 2.6168x; 2.6168x over previous
#include <cuda_runtime.h>
#include <cuda_bf16.h>
#include <stdint.h>

// ---------------- problem constants ----------------
#define DIM        512
#define NPAIR      8192
#define TILE_M     128
#define TILE_N     256
#define NTILES_M   64             // 8192 / 128
#define JITERS     16             // j-iterations per CTA (half range / 256)
#define NKC        8              // K chunks of 64 bf16 (128 B per row)
#define PBLK       16384          // P chunk: 128 rows x 128 B
#define BBLK       32768          // B chunk: 256 rows x 128 B
#define TOTAL_CHUNKS (JITERS * NKC)   // 128

// ---------------- smem layout (offsets from 1024-aligned base) ----------------
#define SM_P       0
#define SM_AB      (SM_P + NKC * PBLK)               // 131072
#define SM_RED     (SM_AB + 2 * BBLK)                // 196608 (double buffer)
#define SM_END     (SM_RED + 128 * 4 * 4)            // 198656
#define SM_DYN     (SM_END + 1024)

// ---------------- device scratch (static: allowed) ----------------
__device__ __nv_bfloat16 g_P[(size_t)NPAIR * DIM];   // normalized positive rows
__device__ __nv_bfloat16 g_A[(size_t)NPAIR * DIM];   // normalized anchor rows
__device__ float g_partial[2 * NPAIR];               // per-half row exp-sums
__device__ float g_diag[NPAIR];                      // fp32 cos_ii (exact)
__device__ float g_blk[32];                          // finalize stage-1 partials

// ---------------- PTX helpers (base-ISA only: no tcgen05 on compute_103) ----------------
static __device__ __forceinline__ uint32_t smem_u32(const void* p) {
    uint32_t a;
    asm("{ .reg .u64 t; cvta.to.shared.u64 t, %1; cvt.u32.u64 %0, t; }"
        : "=r"(a) : "l"(p));
    return a;
}

#define CPA16(dst, src) \
    asm volatile("cp.async.cg.shared.global [%0], [%1], 16;" :: "r"(dst), "l"(src))
#define CPA_COMMIT() asm volatile("cp.async.commit_group;" ::: "memory")
#define CPA_WAIT1()  asm volatile("cp.async.wait_group 1;" ::: "memory")

#define LDSM4(r0, r1, r2, r3, addr) \
    asm volatile("ldmatrix.sync.aligned.m8n8.x4.shared.b16 {%0,%1,%2,%3}, [%4];" \
                 : "=r"(r0), "=r"(r1), "=r"(r2), "=r"(r3) : "r"(addr))

static __device__ __forceinline__ void mma16816(float* d, const uint32_t* a,
                                                const uint32_t* b) {
    asm volatile(
        "mma.sync.aligned.m16n8k16.row.col.f32.bf16.bf16.f32 "
        "{%0,%1,%2,%3}, {%4,%5,%6,%7}, {%8,%9}, {%0,%1,%2,%3};"
        : "+f"(d[0]), "+f"(d[1]), "+f"(d[2]), "+f"(d[3])
        : "r"(a[0]), "r"(a[1]), "r"(a[2]), "r"(a[3]), "r"(b[0]), "r"(b[1]));
}

// ---------------- kernel 1: per-pair normalize + bf16 write + exact fp32 diag ----------------
__global__ void __launch_bounds__(256) prep_kernel(const float* __restrict__ x) {
    int pair = blockIdx.x * 8 + (threadIdx.x >> 5);
    int lid = threadIdx.x & 31;
    const float4* ar = (const float4*)(x + (size_t)(2 * pair) * DIM);      // anchor
    const float4* pr = (const float4*)(x + (size_t)(2 * pair + 1) * DIM);  // positive
    float4 va[4], vp[4];
    float ssa = 0.f, ssp = 0.f, dp = 0.f;
#pragma unroll
    for (int i = 0; i < 4; i++) {
        va[i] = ar[lid + i * 32];
        vp[i] = pr[lid + i * 32];
        ssa += va[i].x * va[i].x + va[i].y * va[i].y + va[i].z * va[i].z + va[i].w * va[i].w;
        ssp += vp[i].x * vp[i].x + vp[i].y * vp[i].y + vp[i].z * vp[i].z + vp[i].w * vp[i].w;
        dp  += va[i].x * vp[i].x + va[i].y * vp[i].y + va[i].z * vp[i].z + va[i].w * vp[i].w;
    }
#pragma unroll
    for (int o = 16; o; o >>= 1) {
        ssa += __shfl_xor_sync(0xffffffffu, ssa, o);
        ssp += __shfl_xor_sync(0xffffffffu, ssp, o);
        dp  += __shfl_xor_sync(0xffffffffu, dp, o);
    }
    float inva = rsqrtf(ssa);   // norms ~sqrt(512): EPS clamp never binds
    float invp = rsqrtf(ssp);
    if (lid == 0) g_diag[pair] = dp * inva * invp;   // exact fp32 diagonal

    __nv_bfloat16* da = g_A + (size_t)pair * DIM;
    __nv_bfloat16* dq = g_P + (size_t)pair * DIM;
#pragma unroll
    for (int i = 0; i < 4; i++) {
        __nv_bfloat162 l0 = __floats2bfloat162_rn(va[i].x * inva, va[i].y * inva);
        __nv_bfloat162 h0 = __floats2bfloat162_rn(va[i].z * inva, va[i].w * inva);
        uint2 pa; pa.x = *(uint32_t*)&l0; pa.y = *(uint32_t*)&h0;
        *(uint2*)(da + (size_t)(lid + i * 32) * 4) = pa;
        __nv_bfloat162 l1 = __floats2bfloat162_rn(vp[i].x * invp, vp[i].y * invp);
        __nv_bfloat162 h1 = __floats2bfloat162_rn(vp[i].z * invp, vp[i].w * invp);
        uint2 pp; pp.x = *(uint32_t*)&l1; pp.y = *(uint32_t*)&h1;
        *(uint2*)(dq + (size_t)(lid + i * 32) * 4) = pp;
    }
}

// ---------------- kernel 2: fused cos-GEMM (bf16 mma, 64x64 warp tile) + exp row-sums ----------------
__global__ void __launch_bounds__(256, 1) angle_main(const float* __restrict__ wp) {
    extern __shared__ char smem_raw[];
    uint32_t sb_raw = smem_u32(smem_raw);
    uint32_t pad = ((sb_raw + 1023u) & ~1023u) - sb_raw;
    char* smem = smem_raw + pad;
    uint32_t sbase = sb_raw + pad;

    const int tid = threadIdx.x, wid = tid >> 5, lid = tid & 31;
    const int wm = wid >> 2, wn = wid & 3;         // 2 x 4 warp grid, 64x64 tiles
    const int it = blockIdx.x >> 1;                // i-tile (positive rows)
    const int half = blockIdx.x & 1;               // anchor half
    const float w = *wp;

    // ldmatrix lane geometry (xor-swizzled 16B chunks within 128B rows)
    const int a_row0 = wm * 64 + (lid & 7) + ((lid >> 3) & 1) * 8;  // + mf*16
    const int a_k = lid >> 4;
    const int a_sw = a_row0 & 7;
    const int b_row0 = wn * 64 + (lid & 7) + ((lid >> 4) & 1) * 8;  // + p*16
    const int b_k = (lid >> 3) & 1;
    const int b_sw = b_row0 & 7;

    // ---- resident P tile: 8 swizzled chunks of [128 rows x 128 B] ----
    {
        const char* src = (const char*)(g_P + (size_t)it * TILE_M * DIM);
        for (int i = tid; i < NKC * 1024; i += 256) {
            int blk = i >> 10, v = i & 1023;
            int row = v >> 3, c = v & 7;
            CPA16(sbase + SM_P + blk * PBLK + row * 128 + ((c ^ (row & 7)) << 4),
                  src + (size_t)row * (DIM * 2) + blk * 128 + c * 16);
        }
        CPA_COMMIT();
    }
    // ---- issue anchor chunk 0 (256 rows x 128 B) ----
    {
        const char* src = (const char*)(g_A + (size_t)(half * JITERS) * TILE_N * DIM);
        for (int u = tid; u < 2048; u += 256) {
            int row = u >> 3, cc = u & 7;
            CPA16(sbase + SM_AB + row * 128 + ((cc ^ (row & 7)) << 4),
                  src + (size_t)row * (DIM * 2) + cc * 16);
        }
        CPA_COMMIT();
    }

    float acc[4][8][4];
#pragma unroll
    for (int mf = 0; mf < 4; mf++)
#pragma unroll
        for (int nf = 0; nf < 8; nf++)
#pragma unroll
            for (int k = 0; k < 4; k++) acc[mf][nf][k] = 0.f;
    float rs[8];
#pragma unroll
    for (int r = 0; r < 8; r++) rs[r] = 0.f;

#pragma unroll 1
    for (int c = 0; c < TOTAL_CHUNKS; ++c) {
        // issue chunk c+1 into the other buffer (prior sync guarantees it's free)
        {
            int cn = c + 1;
            if (cn < TOTAL_CHUNKS) {
                int jt = half * JITERS + (cn >> 3), kc = cn & 7;
                const char* src = (const char*)(g_A + (size_t)jt * TILE_N * DIM) + kc * 128;
                uint32_t dst = sbase + SM_AB + (cn & 1) * BBLK;
                for (int u = tid; u < 2048; u += 256) {
                    int row = u >> 3, cc = u & 7;
                    CPA16(dst + row * 128 + ((cc ^ (row & 7)) << 4),
                          src + (size_t)row * (DIM * 2) + cc * 16);
                }
            }
            CPA_COMMIT();
        }
        CPA_WAIT1();        // chunk c (and P on first iter) resident
        __syncthreads();

        // ---- compute chunk c: 64 k-elems = 4 mma k-steps ----
        const uint32_t pb = sbase + SM_P + (c & 7) * PBLK;
        const uint32_t bb = sbase + SM_AB + (c & 1) * BBLK;
#pragma unroll
        for (int ks = 0; ks < 4; ++ks) {
            uint32_t a[4][4];
#pragma unroll
            for (int mf = 0; mf < 4; ++mf) {
                uint32_t addr = pb + (uint32_t)(a_row0 + mf * 16) * 128 +
                                (uint32_t)(((2 * ks + a_k) ^ a_sw) << 4);
                LDSM4(a[mf][0], a[mf][1], a[mf][2], a[mf][3], addr);
            }
            uint32_t b[8][2];
#pragma unroll
            for (int p = 0; p < 4; ++p) {
                uint32_t addr = bb + (uint32_t)(b_row0 + p * 16) * 128 +
                                (uint32_t)(((2 * ks + b_k) ^ b_sw) << 4);
                uint32_t r0, r1, r2, r3;
                LDSM4(r0, r1, r2, r3, addr);
                b[2 * p][0] = r0; b[2 * p][1] = r1;
                b[2 * p + 1][0] = r2; b[2 * p + 1][1] = r3;
            }
#pragma unroll
            for (int mf = 0; mf < 4; ++mf)
#pragma unroll
                for (int nf = 0; nf < 8; ++nf)
                    mma16816(acc[mf][nf], a[mf], b[nf]);
        }

        // ---- per-j-iter epilogue: exp-accumulate, reset accumulators ----
        if ((c & 7) == 7) {
#pragma unroll
            for (int mf = 0; mf < 4; ++mf)
#pragma unroll
                for (int nf = 0; nf < 8; ++nf) {
                    rs[mf * 2 + 0] += __expf(w * acc[mf][nf][0]) + __expf(w * acc[mf][nf][1]);
                    rs[mf * 2 + 1] += __expf(w * acc[mf][nf][2]) + __expf(w * acc[mf][nf][3]);
#pragma unroll
                    for (int k = 0; k < 4; k++) acc[mf][nf][k] = 0.f;
                }
        }
        __syncthreads();   // all warps done with buf (c&1) before iter c+1 overwrites it
    }

    // ---- deterministic CTA reduction: lanes -> warps(wn) -> rows ----
#pragma unroll
    for (int r = 0; r < 8; ++r) {
        rs[r] += __shfl_xor_sync(0xffffffffu, rs[r], 1);
        rs[r] += __shfl_xor_sync(0xffffffffu, rs[r], 2);
    }
    float* red = (float*)(smem + SM_RED);
    __syncthreads();
    if ((lid & 3) == 0) {
        int g = lid >> 2;
#pragma unroll
        for (int mf = 0; mf < 4; ++mf) {
            int rl0 = wm * 64 + mf * 16 + g;
            red[(rl0) * 4 + wn] = rs[mf * 2 + 0];
            red[(rl0 + 8) * 4 + wn] = rs[mf * 2 + 1];
        }
    }
    __syncthreads();
    if (tid < 128) {
        float s = red[tid * 4 + 0] + red[tid * 4 + 1] + red[tid * 4 + 2] + red[tid * 4 + 3];
        g_partial[half * NPAIR + it * TILE_M + tid] = s;
    }
}

// ---------------- kernel 3: per-row log + block partial (32 CTAs) ----------------
__global__ void __launch_bounds__(256) lse_kernel(const float* __restrict__ wp) {
    __shared__ float red[256];
    int tid = threadIdx.x;
    int i = blockIdx.x * 256 + tid;
    float w = *wp;
    float es = g_partial[i] + g_partial[NPAIR + i];
    red[tid] = logf(es) - w * g_diag[i];
    __syncthreads();
    for (int o = 128; o; o >>= 1) {
        if (tid < o) red[tid] += red[tid + o];
        __syncthreads();
    }
    if (tid == 0) g_blk[blockIdx.x] = red[0];
}

// ---------------- kernel 4: final scalar ----------------
__global__ void finalize_kernel(float* __restrict__ out) {
    int lid = threadIdx.x;
    float s = g_blk[lid];
#pragma unroll
    for (int o = 16; o; o >>= 1) s += __shfl_xor_sync(0xffffffffu, s, o);
    if (lid == 0) out[0] = s / (float)NPAIR;
}

// ---------------- launch ----------------
extern "C" void kernel_launch(void* const* d_in, const int* in_sizes, int n_in,
                              void* d_out, int out_size) {
    const float* x = (const float*)d_in[0];
    const float* wp = (const float*)d_in[1];
    // b cancels analytically: lse_i - logit_ii is independent of b.

    cudaFuncSetAttribute(angle_main, cudaFuncAttributeMaxDynamicSharedMemorySize, SM_DYN);

    prep_kernel<<<NPAIR / 8, 256>>>(x);
    angle_main<<<NTILES_M * 2, 256, SM_DYN>>>(wp);
    lse_kernel<<<32, 256>>>(wp);
    finalize_kernel<<<1, 32>>>((float*)d_out);
}